// round 8
// baseline (speedup 1.0000x reference)
#include <cuda_runtime.h>
#include <math.h>
#include <stdint.h>

#define BATCH   128
#define TT      504
#define TF      502
#define TC      500
#define NSTEP   2000
#define NT      1024
#define BPC     2
#define NCTA    (BATCH / BPC)

// ---------------- transposed-weight offsets (floats) ----------------
#define OFF_FWC    0          // (192,328)
#define OFF_FWCG   62976      // (192,192)
#define OFF_G1IH   99840      // (480,272)
#define OFF_G1HH   230400     // (480,160)
#define OFF_GLU1   307200     // (160,160)
#define OFF_G2IH   332800     // (384,240)
#define OFF_G2HH   424960     // (384,128)
#define OFF_GLU2   474112     // (128,128)
#define OFF_G3IH   490496     // (384,208)
#define OFF_G3HH   570368     // (384,128)
#define OFF_GLU3   619520     // (128,128)
#define OFF_SKIP   635904     // (128,688)
#define OFF_SKIPG  723968     // (128,128)
#define OFF_SIG    740352     // (40,128)
#define OFF_GOUT   745472     // (4,192)
#define WT_TOTAL   746240

// ---------------- device scratch ----------------
__device__ float g_x[BATCH * TF * 64];
__device__ float g_cond[BATCH * TC * 320];
__device__ float g_gain[NSTEP * BATCH];
__device__ float g_wt[WT_TOTAL];

__device__ __forceinline__ float sigf(float x) { return 1.0f / (1.0f + expf(-x)); }

typedef unsigned long long u64;
__device__ __forceinline__ void fma2(u64& d, u64 a, u64 b) {
    asm("fma.rn.f32x2 %0, %1, %2, %3;" : "=l"(d) : "l"(a), "l"(b), "l"(d));
}
__device__ __forceinline__ float2 upk(u64 v) {
    float2 r; asm("mov.b64 {%0, %1}, %2;" : "=f"(r.x), "=f"(r.y) : "l"(v)); return r;
}

// ---------------- fused weight transpose: Wt[k*out+o] = W[o*in+k] ----------------
struct WP { const float* p[15]; };
__constant__ int T_OFF[15] = {OFF_FWC, OFF_FWCG, OFF_G1IH, OFF_G1HH, OFF_GLU1,
                              OFF_G2IH, OFF_G2HH, OFF_GLU2, OFF_G3IH, OFF_G3HH,
                              OFF_GLU3, OFF_SKIP, OFF_SKIPG, OFF_SIG, OFF_GOUT};
__constant__ int T_OUT[15] = {192, 192, 480, 480, 160, 384, 384, 128, 384, 384, 128, 128, 128, 40, 4};
__constant__ int T_IN [15] = {328, 192, 272, 160, 160, 240, 128, 128, 208, 128, 128, 688, 128, 128, 192};

__global__ void k_transpose_all(WP wp) {
    int l = blockIdx.y;
    int i = blockIdx.x * blockDim.x + threadIdx.x;
    int out = T_OUT[l], in = T_IN[l];
    if (i < out * in) {
        int o = i / in, k = i - o * in;
        g_wt[T_OFF[l] + k * out + o] = wp.p[l][i];
    }
}

// ---------------- fd1 ----------------
__global__ void k_fd1(const float* __restrict__ feat, const int* __restrict__ period,
                      const float* __restrict__ pembed, const float* __restrict__ fd1) {
    int bt = blockIdx.x;
    int b = bt / TF, t = bt - b * TF;
    __shared__ float xin[32];
    int tid = threadIdx.x;
    if (tid < 20) {
        xin[tid] = feat[(b * TT + (t + 2)) * 20 + tid];
    } else if (tid < 32) {
        int per = period[b * TT + t + 2];
        per = min(max(per, 32), 254);
        xin[tid] = pembed[(per - 32) * 12 + (tid - 20)];
    }
    __syncthreads();
    float acc = 0.0f;
    const float* w = fd1 + tid * 32;
#pragma unroll
    for (int k = 0; k < 32; k++) acc += w[k] * xin[k];
    g_x[bt * 64 + tid] = tanhf(acc);
}

// ---------------- fused conv1d + fd2 + gain ----------------
__global__ void k_front(const float* __restrict__ wconv, const float* __restrict__ fd2,
                        const float* __restrict__ cg_w, const float* __restrict__ cg_b) {
    int bt = blockIdx.x;
    int b = bt / TC, t = bt - b * TC;
    __shared__ float xin[192];
    __shared__ float ybuf[128];
    __shared__ float condb[320];
    int tid = threadIdx.x;
    for (int i = tid; i < 192; i += 320) {
        xin[i] = g_x[(b * TF + t + (i >> 6)) * 64 + (i & 63)];
    }
    __syncthreads();
    if (tid < 128) {
        float acc = 0.0f;
        const float* w = wconv + tid * 192;
#pragma unroll 8
        for (int ic = 0; ic < 64; ic++) {
            acc += w[ic * 3 + 0] * xin[0 * 64 + ic];
            acc += w[ic * 3 + 1] * xin[1 * 64 + ic];
            acc += w[ic * 3 + 2] * xin[2 * 64 + ic];
        }
        ybuf[tid] = tanhf(acc);
    }
    __syncthreads();
    {
        float acc = 0.0f;
        const float* w = fd2 + tid * 128;
#pragma unroll 8
        for (int k = 0; k < 128; k++) acc += __ldg(w + k) * ybuf[k];
        float c = tanhf(acc);
        condb[tid] = c;
        g_cond[(size_t)bt * 320 + tid] = c;
    }
    __syncthreads();
    if (tid < 4) {
        float acc = cg_b[0];
        const float* c = condb + tid * 80;
#pragma unroll 8
        for (int k = 0; k < 80; k++) acc += cg_w[k] * c[k];
        float g = 0.2f + 0.8f * sigf(acc);
        g = fminf(fmaxf(g, 0.001f), 20.0f);
        g_gain[(t * 4 + tid) * BATCH + b] = g;
    }
}

// ---------------- step context for fused output epilogue ----------------
struct SCtx {
    float* excp;
    const float* sgain;
    float* outp;
    const float* bias;
    int base, step, b0;
};

// ---------------- matvec with fused epilogues ----------------
// Wt [IN][OUT]; x0/x1 duplicated float2 (v,v).
// ACT: 0 none, 1 tanh, 2 glu(aux*sig), 4 pg sigmoid+bias, 5 sig-out.
// DUP: write duplicated pairs to yA0/yA1 (else plain (b0,b1) into yA0).
template <int IN, int OUT, int ACT, int DUP>
__device__ __forceinline__ void mv(const float* __restrict__ Wt,
                                   const float2* __restrict__ x0,
                                   const float2* __restrict__ x1,
                                   float2* __restrict__ yA0, float2* __restrict__ yA1,
                                   const float2* __restrict__ aux0,
                                   const float2* __restrict__ aux1,
                                   float2* __restrict__ red0, float2* __restrict__ red1,
                                   const SCtx& c) {
    constexpr int RG = OUT / 4;
    constexpr int S0n = NT / RG;
    constexpr int S = (S0n > 32) ? 32 : S0n;
    const int tid = threadIdx.x;
    const int sl = tid / RG;
    const int rg = tid - sl * RG;
    if (sl < S) {
        u64 a0 = 0ull, a1 = 0ull, b0 = 0ull, b1 = 0ull;
        const ulonglong2* __restrict__ W2 = reinterpret_cast<const ulonglong2*>(Wt) + rg;
        const u64* __restrict__ xu0 = reinterpret_cast<const u64*>(x0);
        const u64* __restrict__ xu1 = reinterpret_cast<const u64*>(x1);
#pragma unroll 8
        for (int k = sl; k < IN; k += S) {
            ulonglong2 wv = __ldg(&W2[k * RG]);
            u64 xv0 = xu0[k];
            u64 xv1 = xu1[k];
            fma2(a0, wv.x, xv0); fma2(a1, wv.y, xv0);
            fma2(b0, wv.x, xv1); fma2(b1, wv.y, xv1);
        }
        int rb = sl * (OUT / 2) + rg * 2;
        red0[rb] = upk(a0); red0[rb + 1] = upk(a1);
        red1[rb] = upk(b0); red1[rb + 1] = upk(b1);
    }
    __syncthreads();
    // 4-way parallel reduce + 2-level shuffle; fused epilogue in lane q==0
    {
        const int p = tid >> 2, q = tid & 3;
        float2 t0 = make_float2(0.f, 0.f), t1 = make_float2(0.f, 0.f);
        if (p < OUT / 2) {
            for (int ss = q; ss < S; ss += 4) {
                float2 v0 = red0[ss * (OUT / 2) + p];
                float2 v1 = red1[ss * (OUT / 2) + p];
                t0.x += v0.x; t0.y += v0.y; t1.x += v1.x; t1.y += v1.y;
            }
        }
        t0.x += __shfl_xor_sync(0xffffffffu, t0.x, 1);
        t0.y += __shfl_xor_sync(0xffffffffu, t0.y, 1);
        t1.x += __shfl_xor_sync(0xffffffffu, t1.x, 1);
        t1.y += __shfl_xor_sync(0xffffffffu, t1.y, 1);
        t0.x += __shfl_xor_sync(0xffffffffu, t0.x, 2);
        t0.y += __shfl_xor_sync(0xffffffffu, t0.y, 2);
        t1.x += __shfl_xor_sync(0xffffffffu, t1.x, 2);
        t1.y += __shfl_xor_sync(0xffffffffu, t1.y, 2);
        if (q == 0 && p < OUT / 2) {
            int o0 = 2 * p, o1 = 2 * p + 1;
            if (ACT == 0) {
                if (DUP) {
                    yA0[o0] = make_float2(t0.x, t0.x); yA0[o1] = make_float2(t0.y, t0.y);
                    yA1[o0] = make_float2(t1.x, t1.x); yA1[o1] = make_float2(t1.y, t1.y);
                } else {
                    yA0[o0] = make_float2(t0.x, t1.x); yA0[o1] = make_float2(t0.y, t1.y);
                }
            } else if (ACT == 1) {
                float v00 = tanhf(t0.x), v01 = tanhf(t0.y);
                float v10 = tanhf(t1.x), v11 = tanhf(t1.y);
                if (DUP) {
                    yA0[o0] = make_float2(v00, v00); yA0[o1] = make_float2(v01, v01);
                    yA1[o0] = make_float2(v10, v10); yA1[o1] = make_float2(v11, v11);
                } else {
                    yA0[o0] = make_float2(v00, v10); yA0[o1] = make_float2(v01, v11);
                }
            } else if (ACT == 2) {
                float v00 = aux0[o0].x * sigf(t0.x), v01 = aux0[o1].x * sigf(t0.y);
                float v10 = aux1[o0].x * sigf(t1.x), v11 = aux1[o1].x * sigf(t1.y);
                if (DUP) {
                    yA0[o0] = make_float2(v00, v00); yA0[o1] = make_float2(v01, v01);
                    yA1[o0] = make_float2(v10, v10); yA1[o1] = make_float2(v11, v11);
                } else {
                    yA0[o0] = make_float2(v00, v10); yA0[o1] = make_float2(v01, v11);
                }
            } else if (ACT == 4) {
                float b0s = c.bias[o0], b1s = c.bias[o1];
                yA0[o0] = make_float2(sigf(t0.x + b0s), sigf(t1.x + b0s));
                yA0[o1] = make_float2(sigf(t0.y + b1s), sigf(t1.y + b1s));
            } else if (ACT == 5) {
                float v00 = tanhf(t0.x) * c.sgain[0], v01 = tanhf(t0.y) * c.sgain[0];
                float v10 = tanhf(t1.x) * c.sgain[1], v11 = tanhf(t1.y) * c.sgain[1];
                int p0 = (c.base + o0) & 255, p1 = (c.base + o1) & 255;
                c.excp[p0] = v00; c.excp[p1] = v01;
                c.excp[256 + p0] = v10; c.excp[256 + p1] = v11;
                size_t ob = (size_t)c.b0 * 80000 + (size_t)c.step * 40;
                c.outp[ob + o0] = v00; c.outp[ob + o1] = v01;
                c.outp[ob + 80000 + o0] = v10; c.outp[ob + 80000 + o1] = v11;
            }
        }
    }
    __syncthreads();
}

// ---------------- smem layout (float2 units) ----------------
#define O_RED0   0
#define O_RED1   2048
#define O_XC0    4096
#define O_XC1    4424
#define O_BT0    4752
#define O_BT1    4944
#define O_FW0    5136
#define O_FW1    5328
#define O_S10    5520
#define O_S11    5680
#define O_S20    5840
#define O_S21    5968
#define O_S30    6096
#define O_S31    6224
#define O_SKIN0  6352
#define O_SKIN1  7040
#define O_SKV0   7728
#define O_SKV1   7856
#define O_GI     7984
#define O_GH     8464
#define O_G1     8944
#define O_G2     9104
#define O_G3     9232
#define O_PG     9360
#define N_F2     9364
#define SMEM_BYTES (N_F2 * 8 + (2 * 256 + 2 + 2) * 4)

// ---------------- persistent scan: each CTA owns 2 batch chains ----------------
__global__ __launch_bounds__(NT, 1) void k_scan(const int* __restrict__ period,
                                                const float* __restrict__ gout_b,
                                                float* __restrict__ out) {
    int b0 = blockIdx.x * BPC;
    extern __shared__ float2 sm2[];
    float2* red0 = sm2 + O_RED0;
    float2* red1 = sm2 + O_RED1;
    float2* xc0  = sm2 + O_XC0;   // 328 dup, [0:164) state, [164:328) tmp
    float2* xc1  = sm2 + O_XC1;
    float2* bt0  = sm2 + O_BT0;   // 192 dup
    float2* bt1  = sm2 + O_BT1;
    float2* fw0  = sm2 + O_FW0;   // 192 dup
    float2* fw1  = sm2 + O_FW1;
    float2* s10  = sm2 + O_S10;   // 160 dup
    float2* s11  = sm2 + O_S11;
    float2* s20  = sm2 + O_S20;   // 128 dup
    float2* s21  = sm2 + O_S21;
    float2* s30  = sm2 + O_S30;   // 128 dup
    float2* s31  = sm2 + O_S31;
    float2* sk0  = sm2 + O_SKIN0; // 688 dup
    float2* sk1  = sm2 + O_SKIN1;
    float2* sv0  = sm2 + O_SKV0;  // 128 dup
    float2* sv1  = sm2 + O_SKV1;
    float2* gip  = sm2 + O_GI;    // 480 plain (b0,b1)
    float2* ghp  = sm2 + O_GH;    // 480 plain
    float2* g1p  = sm2 + O_G1;    // 160 plain
    float2* g2p  = sm2 + O_G2;    // 128 plain
    float2* g3p  = sm2 + O_G3;    // 128 plain
    float2* pgp  = sm2 + O_PG;    // 4 plain
    float*  excp = (float*)(sm2 + N_F2);  // 2*256
    float*  sgain = excp + 2 * 256;       // 2
    int*    sper  = (int*)(sgain + 2);    // 2
    int tid = threadIdx.x;
    const float* gw = g_wt;

    // init
    for (int i = tid; i < 2 * 256; i += NT) excp[i] = 0.0f;
    float2 z2 = make_float2(0.f, 0.f);
    for (int i = tid; i < 328; i += NT) { xc0[i] = z2; xc1[i] = z2; }
    for (int i = tid; i < 160; i += NT) { s10[i] = z2; s11[i] = z2; }
    for (int i = tid; i < 128; i += NT) { s20[i] = z2; s21[i] = z2; s30[i] = z2; s31[i] = z2; }
    __syncthreads();

    SCtx c;
    c.excp = excp; c.sgain = sgain; c.outp = out; c.bias = gout_b;
    c.base = 0; c.step = 0; c.b0 = b0;

    int base = 0;
    for (int s = 0; s < NSTEP; s++) {
        int frame = s >> 2, sub = s & 3;
        // P0a: scalars + state shift
        if (tid < 2) {
            int p = period[(b0 + tid) * TT + 3 + frame];
            sper[tid] = min(max(p, 32), 254);
        } else if (tid < 4) {
            sgain[tid - 2] = g_gain[s * BATCH + b0 + (tid - 2)];
        }
        if (tid < 328) {
            if (tid < 164) xc0[tid] = xc0[164 + tid];
            else xc1[tid - 164] = xc1[tid];
        }
        __syncthreads();
        // P0b: build tmp = [cond80 | pred44 | prev40] for both batches
        if (tid < 164) {
            int j = tid;
            float v[2];
#pragma unroll
            for (int bb = 0; bb < 2; bb++) {
                float val;
                if (j < 80) {
                    val = g_cond[((size_t)((b0 + bb) * TC + frame)) * 320 + sub * 80 + j];
                } else if (j < 124) {
                    int i2 = j - 80;
                    int idx = 254 - sper[bb] + i2;
                    if (idx >= 256) idx -= sper[bb];
                    idx = max(0, min(255, idx));
                    val = excp[bb * 256 + ((base + idx) & 255)] / (1e-5f + sgain[bb]);
                } else {
                    val = excp[bb * 256 + ((base + 216 + (j - 124)) & 255)] / (1e-5f + sgain[bb]);
                }
                v[bb] = val;
            }
            xc0[164 + j] = make_float2(v[0], v[0]);
            xc1[164 + j] = make_float2(v[1], v[1]);
        }
        __syncthreads();

        // fwc: bt = tanh(fwc_w @ xcat)  -> dup
        mv<328, 192, 1, 1>(gw + OFF_FWC, xc0, xc1, bt0, bt1, 0, 0, red0, red1, c);
        // fwcg + fused GLU: fw = bt * sig(fwc_glu @ bt)  -> dup
        mv<192, 192, 2, 1>(gw + OFF_FWCG, bt0, bt1, fw0, fw1, bt0, bt1, red0, red1, c);
        // pg = sigmoid(gout @ fw + b)  (fused bias+sigmoid)
        mv<192, 4, 4, 0>(gw + OFF_GOUT, fw0, fw1, pgp, 0, 0, 0, red0, red1, c);

        // GRU1 input (272): [fw(192) | pg0*fpitch(40) | prev(40)]  (dup)
        if (tid < 2 * 272) {
            int bb = tid >= 272, j = bb ? tid - 272 : tid;
            const float2* xcd = bb ? xc1 : xc0;
            float vv;
            if (j < 192) vv = (bb ? fw1 : fw0)[j].x;
            else if (j < 232) vv = (bb ? pgp[0].y : pgp[0].x) * xcd[164 + 82 + (j - 192)].x;
            else vv = xcd[164 + 124 + (j - 232)].x;
            (bb ? sk1 : sk0)[j] = make_float2(vv, vv);
        }
        __syncthreads();
        mv<272, 480, 0, 0>(gw + OFF_G1IH, sk0, sk1, gip, 0, 0, 0, red0, red1, c);
        mv<160, 480, 0, 0>(gw + OFF_G1HH, s10, s11, ghp, 0, 0, 0, red0, red1, c);
        // s1 update
        if (tid < 2 * 160) {
            int bb = tid >= 160, j = bb ? tid - 160 : tid;
            const float* gif = (const float*)gip;
            const float* ghf = (const float*)ghp;
            float r = sigf(gif[2 * j + bb] + ghf[2 * j + bb]);
            float z = sigf(gif[2 * (160 + j) + bb] + ghf[2 * (160 + j) + bb]);
            float n = tanhf(gif[2 * (320 + j) + bb] + r * ghf[2 * (320 + j) + bb]);
            float2* sd = bb ? s11 : s10;
            float vv = (1.0f - z) * n + z * sd[j].x;
            sd[j] = make_float2(vv, vv);
        }
        __syncthreads();
        // glu1 fused: g1 = s1 * sig(glu1 @ s1)  (plain)
        mv<160, 160, 2, 0>(gw + OFF_GLU1, s10, s11, g1p, 0, s10, s11, red0, red1, c);

        // GRU2 input (240)
        if (tid < 2 * 240) {
            int bb = tid >= 240, j = bb ? tid - 240 : tid;
            const float2* xcd = bb ? xc1 : xc0;
            float vv;
            if (j < 160) vv = bb ? g1p[j].y : g1p[j].x;
            else if (j < 200) vv = (bb ? pgp[1].y : pgp[1].x) * xcd[164 + 82 + (j - 160)].x;
            else vv = xcd[164 + 124 + (j - 200)].x;
            (bb ? sk1 : sk0)[j] = make_float2(vv, vv);
        }
        __syncthreads();
        mv<240, 384, 0, 0>(gw + OFF_G2IH, sk0, sk1, gip, 0, 0, 0, red0, red1, c);
        mv<128, 384, 0, 0>(gw + OFF_G2HH, s20, s21, ghp, 0, 0, 0, red0, red1, c);
        if (tid < 2 * 128) {
            int bb = tid >= 128, j = bb ? tid - 128 : tid;
            const float* gif = (const float*)gip;
            const float* ghf = (const float*)ghp;
            float r = sigf(gif[2 * j + bb] + ghf[2 * j + bb]);
            float z = sigf(gif[2 * (128 + j) + bb] + ghf[2 * (128 + j) + bb]);
            float n = tanhf(gif[2 * (256 + j) + bb] + r * ghf[2 * (256 + j) + bb]);
            float2* sd = bb ? s21 : s20;
            float vv = (1.0f - z) * n + z * sd[j].x;
            sd[j] = make_float2(vv, vv);
        }
        __syncthreads();
        mv<128, 128, 2, 0>(gw + OFF_GLU2, s20, s21, g2p, 0, s20, s21, red0, red1, c);

        // GRU3 input (208)
        if (tid < 2 * 208) {
            int bb = tid >= 208, j = bb ? tid - 208 : tid;
            const float2* xcd = bb ? xc1 : xc0;
            float vv;
            if (j < 128) vv = bb ? g2p[j].y : g2p[j].x;
            else if (j < 168) vv = (bb ? pgp[2].y : pgp[2].x) * xcd[164 + 82 + (j - 128)].x;
            else vv = xcd[164 + 124 + (j - 168)].x;
            (bb ? sk1 : sk0)[j] = make_float2(vv, vv);
        }
        __syncthreads();
        mv<208, 384, 0, 0>(gw + OFF_G3IH, sk0, sk1, gip, 0, 0, 0, red0, red1, c);
        mv<128, 384, 0, 0>(gw + OFF_G3HH, s30, s31, ghp, 0, 0, 0, red0, red1, c);
        if (tid < 2 * 128) {
            int bb = tid >= 128, j = bb ? tid - 128 : tid;
            const float* gif = (const float*)gip;
            const float* ghf = (const float*)ghp;
            float r = sigf(gif[2 * j + bb] + ghf[2 * j + bb]);
            float z = sigf(gif[2 * (128 + j) + bb] + ghf[2 * (128 + j) + bb]);
            float n = tanhf(gif[2 * (256 + j) + bb] + r * ghf[2 * (256 + j) + bb]);
            float2* sd = bb ? s31 : s30;
            float vv = (1.0f - z) * n + z * sd[j].x;
            sd[j] = make_float2(vv, vv);
        }
        __syncthreads();
        mv<128, 128, 2, 0>(gw + OFF_GLU3, s30, s31, g3p, 0, s30, s31, red0, red1, c);

        // skip_in (688): [g1 | g2 | g3 | fw | pg3*fpitch | prev]
        for (int i = tid; i < 2 * 688; i += NT) {
            int bb = i >= 688, j = bb ? i - 688 : i;
            const float2* xcd = bb ? xc1 : xc0;
            float vv;
            if (j < 160) vv = bb ? g1p[j].y : g1p[j].x;
            else if (j < 288) vv = bb ? g2p[j - 160].y : g2p[j - 160].x;
            else if (j < 416) vv = bb ? g3p[j - 288].y : g3p[j - 288].x;
            else if (j < 608) vv = (bb ? fw1 : fw0)[j - 416].x;
            else if (j < 648) vv = (bb ? pgp[3].y : pgp[3].x) * xcd[164 + 82 + (j - 608)].x;
            else vv = xcd[164 + 124 + (j - 648)].x;
            (bb ? sk1 : sk0)[j] = make_float2(vv, vv);
        }
        __syncthreads();
        mv<688, 128, 1, 1>(gw + OFF_SKIP, sk0, sk1, bt0, bt1, 0, 0, red0, red1, c);
        // skip glu fused: sv = bt * sig(skipg @ bt)  (dup)
        mv<128, 128, 2, 1>(gw + OFF_SKIPG, bt0, bt1, sv0, sv1, bt0, bt1, red0, red1, c);

        // sig = tanh(sig_w @ sv) * gain -> exc push + output (fused)
        c.base = base; c.step = s;
        mv<128, 40, 5, 0>(gw + OFF_SIG, sv0, sv1, 0, 0, 0, 0, red0, red1, c);
        base = (base + 40) & 255;
    }
}

// ---------------- launch ----------------
extern "C" void kernel_launch(void* const* d_in, const int* in_sizes, int n_in,
                              void* d_out, int out_size) {
    const float* features = (const float*)d_in[0];
    const int*   period   = (const int*)d_in[1];
    const float* pembed   = (const float*)d_in[2];
    const float* fd1_w    = (const float*)d_in[3];
    const float* fconv1_w = (const float*)d_in[4];
    const float* fd2_w    = (const float*)d_in[5];
    const float* cg_w     = (const float*)d_in[6];
    const float* cg_b     = (const float*)d_in[7];
    const float* gout_b   = (const float*)d_in[23];
    float* out = (float*)d_out;

    WP wp;
    for (int i = 0; i < 15; i++) wp.p[i] = (const float*)d_in[8 + i];

    cudaFuncSetAttribute(k_scan, cudaFuncAttributeMaxDynamicSharedMemorySize, SMEM_BYTES);

    dim3 tg((130560 + 255) / 256, 15);
    k_transpose_all<<<tg, 256>>>(wp);
    k_fd1<<<BATCH * TF, 64>>>(features, period, pembed, fd1_w);
    k_front<<<BATCH * TC, 320>>>(fconv1_w, fd2_w, cg_w, cg_b);
    k_scan<<<NCTA, NT, SMEM_BYTES>>>(period, gout_b, out);
    (void)in_sizes; (void)n_in; (void)out_size;
}

// round 10
// speedup vs baseline: 1.5309x; 1.5309x over previous
#include <cuda_runtime.h>
#include <math.h>
#include <stdint.h>

#define BATCH   128
#define TT      504
#define TF      502
#define TC      500
#define NSTEP   2000
#define NT      512
#define BPC     2
#define NCTA    (BATCH / BPC)

// ---------------- transposed-weight offsets (floats) ----------------
#define OFF_FWC    0          // (192,328)
#define OFF_FWCG   62976      // (192,192)
#define OFF_G1IH   99840      // (480,272)
#define OFF_G1HH   230400     // (480,160)
#define OFF_GLU1   307200     // (160,160)
#define OFF_G2IH   332800     // (384,240)
#define OFF_G2HH   424960     // (384,128)
#define OFF_GLU2   474112     // (128,128)
#define OFF_G3IH   490496     // (384,208)
#define OFF_G3HH   570368     // (384,128)
#define OFF_GLU3   619520     // (128,128)
#define OFF_SKIP   635904     // (128,688)
#define OFF_SKIPG  723968     // (128,128)
#define OFF_SIG    740352     // (40,128)
#define OFF_GOUT   745472     // (4,192)
#define WT_TOTAL   746240

// ---------------- device scratch ----------------
__device__ float g_x[BATCH * TF * 64];
__device__ float g_cond[BATCH * TC * 320];
__device__ float g_gain[NSTEP * BATCH];
__device__ float g_wt[WT_TOTAL];

__device__ __forceinline__ float sigf(float x) { return 1.0f / (1.0f + expf(-x)); }

// ---------------- fused weight transpose: Wt[k*out+o] = W[o*in+k] ----------------
struct WP { const float* p[15]; };
__constant__ int T_OFF[15] = {OFF_FWC, OFF_FWCG, OFF_G1IH, OFF_G1HH, OFF_GLU1,
                              OFF_G2IH, OFF_G2HH, OFF_GLU2, OFF_G3IH, OFF_G3HH,
                              OFF_GLU3, OFF_SKIP, OFF_SKIPG, OFF_SIG, OFF_GOUT};
__constant__ int T_OUT[15] = {192, 192, 480, 480, 160, 384, 384, 128, 384, 384, 128, 128, 128, 40, 4};
__constant__ int T_IN [15] = {328, 192, 272, 160, 160, 240, 128, 128, 208, 128, 128, 688, 128, 128, 192};

__global__ void k_transpose_all(WP wp) {
    int l = blockIdx.y;
    int i = blockIdx.x * blockDim.x + threadIdx.x;
    int out = T_OUT[l], in = T_IN[l];
    if (i < out * in) {
        int o = i / in, k = i - o * in;
        g_wt[T_OFF[l] + k * out + o] = wp.p[l][i];
    }
}

// ---------------- fd1 ----------------
__global__ void k_fd1(const float* __restrict__ feat, const int* __restrict__ period,
                      const float* __restrict__ pembed, const float* __restrict__ fd1) {
    int bt = blockIdx.x;
    int b = bt / TF, t = bt - b * TF;
    __shared__ float xin[32];
    int tid = threadIdx.x;
    if (tid < 20) {
        xin[tid] = feat[(b * TT + (t + 2)) * 20 + tid];
    } else if (tid < 32) {
        int per = period[b * TT + t + 2];
        per = min(max(per, 32), 254);
        xin[tid] = pembed[(per - 32) * 12 + (tid - 20)];
    }
    __syncthreads();
    float acc = 0.0f;
    const float* w = fd1 + tid * 32;
#pragma unroll
    for (int k = 0; k < 32; k++) acc += w[k] * xin[k];
    g_x[bt * 64 + tid] = tanhf(acc);
}

// ---------------- fused conv1d + fd2 + gain ----------------
__global__ void k_front(const float* __restrict__ wconv, const float* __restrict__ fd2,
                        const float* __restrict__ cg_w, const float* __restrict__ cg_b) {
    int bt = blockIdx.x;
    int b = bt / TC, t = bt - b * TC;
    __shared__ float xin[192];
    __shared__ float ybuf[128];
    __shared__ float condb[320];
    int tid = threadIdx.x;
    for (int i = tid; i < 192; i += 320) {
        xin[i] = g_x[(b * TF + t + (i >> 6)) * 64 + (i & 63)];
    }
    __syncthreads();
    if (tid < 128) {
        float acc = 0.0f;
        const float* w = wconv + tid * 192;
#pragma unroll 8
        for (int ic = 0; ic < 64; ic++) {
            acc += w[ic * 3 + 0] * xin[0 * 64 + ic];
            acc += w[ic * 3 + 1] * xin[1 * 64 + ic];
            acc += w[ic * 3 + 2] * xin[2 * 64 + ic];
        }
        ybuf[tid] = tanhf(acc);
    }
    __syncthreads();
    {
        float acc = 0.0f;
        const float* w = fd2 + tid * 128;
#pragma unroll 8
        for (int k = 0; k < 128; k++) acc += __ldg(w + k) * ybuf[k];
        float c = tanhf(acc);
        condb[tid] = c;
        g_cond[(size_t)bt * 320 + tid] = c;
    }
    __syncthreads();
    if (tid < 4) {
        float acc = cg_b[0];
        const float* c = condb + tid * 80;
#pragma unroll 8
        for (int k = 0; k < 80; k++) acc += cg_w[k] * c[k];
        float g = 0.2f + 0.8f * sigf(acc);
        g = fminf(fmaxf(g, 0.001f), 20.0f);
        g_gain[(t * 4 + tid) * BATCH + b] = g;
    }
}

// ---------------- matvec mainloop: contiguous-k slices, float4 x broadcast ----------------
// Wt [IN][OUT] transposed. Writes partials to redA0/redA1 (slice-major, S x OUT).
template <int IN, int OUT>
__device__ __forceinline__ void mv_main(const float* __restrict__ Wt,
                                        const float* __restrict__ x0,
                                        const float* __restrict__ x1,
                                        float* __restrict__ redA0,
                                        float* __restrict__ redA1) {
    constexpr int RG = OUT / 4;
    constexpr int S0n = NT / RG;
    constexpr int S = (S0n > 32) ? 32 : S0n;
    constexpr int CH = (((IN + S - 1) / S) + 3) & ~3;   // contiguous chunk, mult of 4
    const int tid = threadIdx.x;
    const int sl = tid / RG;
    const int rg = tid - sl * RG;
    if (sl < S) {
        float4 a0 = make_float4(0.f, 0.f, 0.f, 0.f);
        float4 a1 = make_float4(0.f, 0.f, 0.f, 0.f);
        int k0 = sl * CH;
        int k1 = k0 + CH; if (k1 > IN) k1 = IN;
        const float4* __restrict__ W4 = reinterpret_cast<const float4*>(Wt) + rg;
#pragma unroll 2
        for (int k = k0; k < k1; k += 4) {
            float4 xv0 = *reinterpret_cast<const float4*>(x0 + k);
            float4 xv1 = *reinterpret_cast<const float4*>(x1 + k);
#pragma unroll
            for (int u = 0; u < 4; u++) {
                float4 w = __ldg(&W4[(k + u) * RG]);
                float p0 = (u == 0) ? xv0.x : (u == 1) ? xv0.y : (u == 2) ? xv0.z : xv0.w;
                float p1 = (u == 0) ? xv1.x : (u == 1) ? xv1.y : (u == 2) ? xv1.z : xv1.w;
                a0.x = fmaf(w.x, p0, a0.x); a0.y = fmaf(w.y, p0, a0.y);
                a0.z = fmaf(w.z, p0, a0.z); a0.w = fmaf(w.w, p0, a0.w);
                a1.x = fmaf(w.x, p1, a1.x); a1.y = fmaf(w.y, p1, a1.y);
                a1.z = fmaf(w.z, p1, a1.z); a1.w = fmaf(w.w, p1, a1.w);
            }
        }
        *(reinterpret_cast<float4*>(redA0 + sl * OUT) + rg) = a0;
        *(reinterpret_cast<float4*>(redA1 + sl * OUT) + rg) = a1;
    }
}

// ---------------- reduce with fused epilogues ----------------
// ACT: 0 none, 1 tanh, 2 glu(aux*sig), 4 pg sigmoid+bias
template <int OUT, int ACT>
__device__ __forceinline__ void mv_reduce(const float* __restrict__ redA0,
                                          const float* __restrict__ redA1,
                                          float* __restrict__ y0, float* __restrict__ y1,
                                          const float* __restrict__ aux0,
                                          const float* __restrict__ aux1,
                                          const float* __restrict__ bias) {
    constexpr int RG = OUT / 4;
    constexpr int S0n = NT / RG;
    constexpr int S = (S0n > 32) ? 32 : S0n;
    const int tid = threadIdx.x;
    for (int o = tid; o < 2 * OUT; o += NT) {
        int bb = o >= OUT;
        int j = bb ? o - OUT : o;
        const float* r = bb ? redA1 : redA0;
        float t = 0.0f;
#pragma unroll
        for (int ss = 0; ss < S; ss++) t += r[ss * OUT + j];
        float* y = bb ? y1 : y0;
        if (ACT == 0) y[j] = t;
        else if (ACT == 1) y[j] = tanhf(t);
        else if (ACT == 2) y[j] = (bb ? aux1 : aux0)[j] * sigf(t);
        else if (ACT == 4) y[j] = sigf(t + bias[j]);
    }
}

// ---------------- fused GRU reduce + state update ----------------
template <int H>
__device__ __forceinline__ void gru_reduce(const float* __restrict__ redA0,
                                           const float* __restrict__ redA1,
                                           const float* __restrict__ redB0,
                                           const float* __restrict__ redB1,
                                           float* __restrict__ s0, float* __restrict__ s1v) {
    constexpr int OUT = 3 * H;
    constexpr int RG = OUT / 4;
    constexpr int S0n = NT / RG;
    constexpr int S = (S0n > 32) ? 32 : S0n;
    const int tid = threadIdx.x;
    for (int idx = tid; idx < 2 * H; idx += NT) {
        int bb = idx >= H;
        int o = bb ? idx - H : idx;
        const float* rA = bb ? redA1 : redA0;
        const float* rB = bb ? redB1 : redB0;
        float gr = 0.f, gz = 0.f, gn = 0.f, hr = 0.f, hz = 0.f, hn = 0.f;
#pragma unroll
        for (int ss = 0; ss < S; ss++) {
            const float* a = rA + ss * OUT;
            const float* b = rB + ss * OUT;
            gr += a[o]; gz += a[H + o]; gn += a[2 * H + o];
            hr += b[o]; hz += b[H + o]; hn += b[2 * H + o];
        }
        float r = sigf(gr + hr);
        float z = sigf(gz + hz);
        float n = tanhf(gn + r * hn);
        float* sd = bb ? s1v : s0;
        sd[o] = (1.0f - z) * n + z * sd[o];
    }
}

// ---------------- smem layout (float offsets; all mult of 4) ----------------
#define O_REDA0  0
#define O_REDA1  2048
#define O_REDB0  4096
#define O_REDB1  6144
#define O_XC0    8192
#define O_XC1    8520
#define O_BT0    8848
#define O_BT1    9040
#define O_FW0    9232
#define O_FW1    9424
#define O_S10    9616
#define O_S11    9776
#define O_S20    9936
#define O_S21    10064
#define O_S30    10192
#define O_S31    10320
#define O_G10    10448
#define O_G11    10608
#define O_G20    10768
#define O_G21    10896
#define O_G30    11024
#define O_G31    11152
#define O_SK0    11280
#define O_SK1    11968
#define O_SV0    12656
#define O_SV1    12784
#define O_PG0    12912
#define O_PG1    12916
#define O_EXC    12920
#define O_GAIN   13432
#define O_PER    13436
#define N_FL     13440
#define SMEM_BYTES (N_FL * 4)

// ---------------- persistent scan: each CTA owns 2 batch chains ----------------
__global__ __launch_bounds__(NT, 1) void k_scan(const int* __restrict__ period,
                                                const float* __restrict__ gout_b,
                                                float* __restrict__ out) {
    int b0 = blockIdx.x * BPC;
    extern __shared__ float sm[];
    float* redA0 = sm + O_REDA0;
    float* redA1 = sm + O_REDA1;
    float* redB0 = sm + O_REDB0;
    float* redB1 = sm + O_REDB1;
    float* xc0 = sm + O_XC0;   // 328: [0:164) state, [164:328) tmp
    float* xc1 = sm + O_XC1;
    float* bt0 = sm + O_BT0;   // 192
    float* bt1 = sm + O_BT1;
    float* fw0 = sm + O_FW0;   // 192
    float* fw1 = sm + O_FW1;
    float* s10 = sm + O_S10;   // 160
    float* s11 = sm + O_S11;
    float* s20 = sm + O_S20;   // 128
    float* s21 = sm + O_S21;
    float* s30 = sm + O_S30;
    float* s31 = sm + O_S31;
    float* g10 = sm + O_G10;   // 160
    float* g11 = sm + O_G11;
    float* g20 = sm + O_G20;   // 128
    float* g21 = sm + O_G21;
    float* g30 = sm + O_G30;
    float* g31 = sm + O_G31;
    float* sk0 = sm + O_SK0;   // 688
    float* sk1 = sm + O_SK1;
    float* sv0 = sm + O_SV0;   // 128
    float* sv1 = sm + O_SV1;
    float* pg0 = sm + O_PG0;   // 4
    float* pg1 = sm + O_PG1;
    float* excp = sm + O_EXC;  // 2*256
    float* sgain = sm + O_GAIN;
    int*   sper  = (int*)(sm + O_PER);
    int tid = threadIdx.x;
    const float* gw = g_wt;

    // init
    for (int i = tid; i < 2 * 256; i += NT) excp[i] = 0.0f;
    for (int i = tid; i < 328; i += NT) { xc0[i] = 0.0f; xc1[i] = 0.0f; }
    for (int i = tid; i < 160; i += NT) { s10[i] = 0.0f; s11[i] = 0.0f; }
    for (int i = tid; i < 128; i += NT) { s20[i] = 0.0f; s21[i] = 0.0f; s30[i] = 0.0f; s31[i] = 0.0f; }
    __syncthreads();

    int base = 0;
    for (int s = 0; s < NSTEP; s++) {
        int frame = s >> 2, sub = s & 3;

        // P0a: scalars + state shift
        if (tid < 2) {
            int p = period[(b0 + tid) * TT + 3 + frame];
            sper[tid] = min(max(p, 32), 254);
        } else if (tid < 4) {
            sgain[tid - 2] = g_gain[s * BATCH + b0 + (tid - 2)];
        }
        if (tid < 328) {
            if (tid < 164) xc0[tid] = xc0[164 + tid];
            else xc1[tid - 164] = xc1[tid];
        }
        __syncthreads();

        // P0b: build tmp = [cond80 | pred44 | prev40]
        if (tid < 164) {
            int j = tid;
            float v0 = 0.f, v1 = 0.f;
#pragma unroll
            for (int bb = 0; bb < 2; bb++) {
                float val;
                if (j < 80) {
                    val = g_cond[((size_t)((b0 + bb) * TC + frame)) * 320 + sub * 80 + j];
                } else if (j < 124) {
                    int i2 = j - 80;
                    int idx = 254 - sper[bb] + i2;
                    if (idx >= 256) idx -= sper[bb];
                    idx = max(0, min(255, idx));
                    val = excp[bb * 256 + ((base + idx) & 255)] / (1e-5f + sgain[bb]);
                } else {
                    val = excp[bb * 256 + ((base + 216 + (j - 124)) & 255)] / (1e-5f + sgain[bb]);
                }
                if (bb == 0) v0 = val; else v1 = val;
            }
            xc0[164 + j] = v0;
            xc1[164 + j] = v1;
        }
        __syncthreads();

        // fwc main + reduce(tanh) -> bt
        mv_main<328, 192>(gw + OFF_FWC, xc0, xc1, redA0, redA1);
        __syncthreads();
        mv_reduce<192, 1>(redA0, redA1, bt0, bt1, 0, 0, 0);
        __syncthreads();

        // fwcg main + reduce(glu aux=bt) -> fw
        mv_main<192, 192>(gw + OFF_FWCG, bt0, bt1, redA0, redA1);
        __syncthreads();
        mv_reduce<192, 2>(redA0, redA1, fw0, fw1, bt0, bt1, 0);
        __syncthreads();

        // gout main + reduce(sig+bias) -> pg
        mv_main<192, 4>(gw + OFF_GOUT, fw0, fw1, redA0, redA1);
        __syncthreads();
        mv_reduce<4, 4>(redA0, redA1, pg0, pg1, 0, 0, gout_b);
        __syncthreads();

        // GRU1 input (272): [fw(192) | pg0*fpitch(40) | prev(40)]
        // NOTE: 2*272 = 544 > NT, MUST be a grid-stride loop (R9 bug: single-shot if)
        for (int i = tid; i < 2 * 272; i += NT) {
            int bb = i >= 272, j = bb ? i - 272 : i;
            const float* xcd = bb ? xc1 : xc0;
            float vv;
            if (j < 192) vv = (bb ? fw1 : fw0)[j];
            else if (j < 232) vv = (bb ? pg1 : pg0)[0] * xcd[164 + 82 + (j - 192)];
            else vv = xcd[164 + 124 + (j - 232)];
            (bb ? sk1 : sk0)[j] = vv;
        }
        __syncthreads();
        // gru1 mains (ih + hh) + fused reduce/update
        mv_main<272, 480>(gw + OFF_G1IH, sk0, sk1, redA0, redA1);
        mv_main<160, 480>(gw + OFF_G1HH, s10, s11, redB0, redB1);
        __syncthreads();
        gru_reduce<160>(redA0, redA1, redB0, redB1, s10, s11);
        __syncthreads();
        // glu1 main + reduce(glu aux=s1) -> g1
        mv_main<160, 160>(gw + OFF_GLU1, s10, s11, redA0, redA1);
        __syncthreads();
        mv_reduce<160, 2>(redA0, redA1, g10, g11, s10, s11, 0);
        __syncthreads();

        // GRU2 input (240): [g1 | pg1*fpitch | prev]
        if (tid < 2 * 240) {
            int bb = tid >= 240, j = bb ? tid - 240 : tid;
            const float* xcd = bb ? xc1 : xc0;
            float vv;
            if (j < 160) vv = (bb ? g11 : g10)[j];
            else if (j < 200) vv = (bb ? pg1 : pg0)[1] * xcd[164 + 82 + (j - 160)];
            else vv = xcd[164 + 124 + (j - 200)];
            (bb ? sk1 : sk0)[j] = vv;
        }
        __syncthreads();
        mv_main<240, 384>(gw + OFF_G2IH, sk0, sk1, redA0, redA1);
        mv_main<128, 384>(gw + OFF_G2HH, s20, s21, redB0, redB1);
        __syncthreads();
        gru_reduce<128>(redA0, redA1, redB0, redB1, s20, s21);
        __syncthreads();
        mv_main<128, 128>(gw + OFF_GLU2, s20, s21, redA0, redA1);
        __syncthreads();
        mv_reduce<128, 2>(redA0, redA1, g20, g21, s20, s21, 0);
        __syncthreads();

        // GRU3 input (208): [g2 | pg2*fpitch | prev]
        if (tid < 2 * 208) {
            int bb = tid >= 208, j = bb ? tid - 208 : tid;
            const float* xcd = bb ? xc1 : xc0;
            float vv;
            if (j < 128) vv = (bb ? g21 : g20)[j];
            else if (j < 168) vv = (bb ? pg1 : pg0)[2] * xcd[164 + 82 + (j - 128)];
            else vv = xcd[164 + 124 + (j - 168)];
            (bb ? sk1 : sk0)[j] = vv;
        }
        __syncthreads();
        mv_main<208, 384>(gw + OFF_G3IH, sk0, sk1, redA0, redA1);
        mv_main<128, 384>(gw + OFF_G3HH, s30, s31, redB0, redB1);
        __syncthreads();
        gru_reduce<128>(redA0, redA1, redB0, redB1, s30, s31);
        __syncthreads();
        mv_main<128, 128>(gw + OFF_GLU3, s30, s31, redA0, redA1);
        __syncthreads();
        mv_reduce<128, 2>(redA0, redA1, g30, g31, s30, s31, 0);
        __syncthreads();

        // skip_in (688): [g1 | g2 | g3 | fw | pg3*fpitch | prev]
        for (int i = tid; i < 2 * 688; i += NT) {
            int bb = i >= 688, j = bb ? i - 688 : i;
            const float* xcd = bb ? xc1 : xc0;
            float vv;
            if (j < 160) vv = (bb ? g11 : g10)[j];
            else if (j < 288) vv = (bb ? g21 : g20)[j - 160];
            else if (j < 416) vv = (bb ? g31 : g30)[j - 288];
            else if (j < 608) vv = (bb ? fw1 : fw0)[j - 416];
            else if (j < 648) vv = (bb ? pg1 : pg0)[3] * xcd[164 + 82 + (j - 608)];
            else vv = xcd[164 + 124 + (j - 648)];
            (bb ? sk1 : sk0)[j] = vv;
        }
        __syncthreads();
        // skip main + reduce(tanh) -> bt
        mv_main<688, 128>(gw + OFF_SKIP, sk0, sk1, redA0, redA1);
        __syncthreads();
        mv_reduce<128, 1>(redA0, redA1, bt0, bt1, 0, 0, 0);
        __syncthreads();
        // skipg main + reduce(glu aux=bt) -> sv
        mv_main<128, 128>(gw + OFF_SKIPG, bt0, bt1, redA0, redA1);
        __syncthreads();
        mv_reduce<128, 2>(redA0, redA1, sv0, sv1, bt0, bt1, 0);
        __syncthreads();

        // sig main + fused output reduce
        mv_main<128, 40>(gw + OFF_SIG, sv0, sv1, redA0, redA1);
        __syncthreads();
        {
            constexpr int S = 32;
            if (tid < 2 * 40) {
                int bb = tid >= 40, j = bb ? tid - 40 : tid;
                const float* r = bb ? redA1 : redA0;
                float t = 0.0f;
#pragma unroll
                for (int ss = 0; ss < S; ss++) t += r[ss * 40 + j];
                float vv = tanhf(t) * sgain[bb];
                excp[bb * 256 + ((base + j) & 255)] = vv;
                out[(size_t)(b0 + bb) * 80000 + (size_t)s * 40 + j] = vv;
            }
        }
        __syncthreads();
        base = (base + 40) & 255;
    }
}

// ---------------- launch ----------------
extern "C" void kernel_launch(void* const* d_in, const int* in_sizes, int n_in,
                              void* d_out, int out_size) {
    const float* features = (const float*)d_in[0];
    const int*   period   = (const int*)d_in[1];
    const float* pembed   = (const float*)d_in[2];
    const float* fd1_w    = (const float*)d_in[3];
    const float* fconv1_w = (const float*)d_in[4];
    const float* fd2_w    = (const float*)d_in[5];
    const float* cg_w     = (const float*)d_in[6];
    const float* cg_b     = (const float*)d_in[7];
    const float* gout_b   = (const float*)d_in[23];
    float* out = (float*)d_out;

    WP wp;
    for (int i = 0; i < 15; i++) wp.p[i] = (const float*)d_in[8 + i];

    cudaFuncSetAttribute(k_scan, cudaFuncAttributeMaxDynamicSharedMemorySize, SMEM_BYTES);

    dim3 tg((130560 + 255) / 256, 15);
    k_transpose_all<<<tg, 256>>>(wp);
    k_fd1<<<BATCH * TF, 64>>>(features, period, pembed, fd1_w);
    k_front<<<BATCH * TC, 320>>>(fconv1_w, fd2_w, cg_w, cg_b);
    k_scan<<<NCTA, NT, SMEM_BYTES>>>(period, gout_b, out);
    (void)in_sizes; (void)n_in; (void)out_size;
}

// round 12
// speedup vs baseline: 2.4267x; 1.5851x over previous
#include <cuda_runtime.h>
#include <math.h>
#include <stdint.h>

#define BATCH   128
#define TT      504
#define TF      502      // tokens after features[:,2:]
#define TC      500      // cond frames
#define NSTEP   2000
#define NT      512      // threads in scan CTA

// ---------------- transposed-weight offsets (floats) ----------------
#define OFF_FWC    0          // (192,328)
#define OFF_FWCG   62976      // (192,192)
#define OFF_G1IH   99840      // (480,272)
#define OFF_G1HH   230400     // (480,160)
#define OFF_GLU1   307200     // (160,160)
#define OFF_G2IH   332800     // (384,240)
#define OFF_G2HH   424960     // (384,128)
#define OFF_GLU2   474112     // (128,128)
#define OFF_G3IH   490496     // (384,208)
#define OFF_G3HH   570368     // (384,128)
#define OFF_GLU3   619520     // (128,128)
#define OFF_SKIP   635904     // (128,688)
#define OFF_SKIPG  723968     // (128,128)
#define OFF_SIG    740352     // (40,128)
#define OFF_GOUT   745472     // (4,192)
#define WT_TOTAL   746240

// ---------------- device scratch ----------------
__device__ float g_x[BATCH * TF * 64];        // fd1 output
__device__ float g_y[BATCH * TC * 128];       // conv output
__device__ float g_cond[BATCH * TC * 320];    // fd2 output
__device__ float g_gain[NSTEP * BATCH];       // precomputed gains
__device__ float g_wt[WT_TOTAL];              // transposed weights [in][out]

__device__ __forceinline__ float sigf(float x) { return 1.0f / (1.0f + expf(-x)); }

// ---------------- fused weight transpose: Wt[k*out+o] = W[o*in+k] ----------------
struct WP { const float* p[15]; };
__constant__ int T_OFF[15] = {OFF_FWC, OFF_FWCG, OFF_G1IH, OFF_G1HH, OFF_GLU1,
                              OFF_G2IH, OFF_G2HH, OFF_GLU2, OFF_G3IH, OFF_G3HH,
                              OFF_GLU3, OFF_SKIP, OFF_SKIPG, OFF_SIG, OFF_GOUT};
__constant__ int T_OUT[15] = {192, 192, 480, 480, 160, 384, 384, 128, 384, 384, 128, 128, 128, 40, 4};
__constant__ int T_IN [15] = {328, 192, 272, 160, 160, 240, 128, 128, 208, 128, 128, 688, 128, 128, 192};

__global__ void k_transpose_all(WP wp) {
    int l = blockIdx.y;
    int i = blockIdx.x * blockDim.x + threadIdx.x;
    int out = T_OUT[l], in = T_IN[l];
    if (i < out * in) {
        int o = i / in, k = i - o * in;
        g_wt[T_OFF[l] + k * out + o] = wp.p[l][i];
    }
}

// ---------------- fd1: weight-stationary, 1 block per batch elem ----------------
// warp-per-token; xin distributed across lanes, broadcast via shfl.
__global__ void k_fd1n(const float* __restrict__ feat, const int* __restrict__ period,
                       const float* __restrict__ pembed, const float* __restrict__ fd1) {
    int b = blockIdx.x;
    __shared__ float wd1[64 * 33];   // padded stride 33 -> conflict-free
    int tid = threadIdx.x;           // 256
    for (int i = tid; i < 64 * 32; i += 256) {
        int o = i >> 5, k = i & 31;
        wd1[o * 33 + k] = fd1[i];
    }
    __syncthreads();
    int warp = tid >> 5, lane = tid & 31;
    for (int t = warp; t < TF; t += 8) {
        int per = period[b * TT + t + 2];
        per = min(max(per, 32), 254);
        float v;
        if (lane < 20) v = feat[(b * TT + t + 2) * 20 + lane];
        else           v = pembed[(per - 32) * 12 + (lane - 20)];
        float a0 = 0.0f, a1 = 0.0f;
#pragma unroll
        for (int k = 0; k < 32; k++) {
            float xk = __shfl_sync(0xffffffffu, v, k);
            a0 = fmaf(wd1[lane * 33 + k], xk, a0);
            a1 = fmaf(wd1[(lane + 32) * 33 + k], xk, a1);
        }
        g_x[(b * TF + t) * 64 + lane] = tanhf(a0);
        g_x[(b * TF + t) * 64 + lane + 32] = tanhf(a1);
    }
}

// ---------------- conv1d: weight-stationary, 2 blocks per batch elem ----------------
#define CONV_SMEM ((128 * 193 + 192) * 4)
__global__ void k_convn(const float* __restrict__ wconv) {
    int b = blockIdx.x;
    int t0 = blockIdx.y * 250;
    extern __shared__ float smc[];
    float* wc = smc;                 // 128 x 193 (padded)
    float* xin = smc + 128 * 193;    // 192
    int tid = threadIdx.x;           // 128
    for (int i = tid; i < 128 * 192; i += 128) {
        int oc = i / 192, k = i - oc * 192;
        wc[oc * 193 + k] = wconv[i];
    }
    __syncthreads();
    for (int t = t0; t < t0 + 250; t++) {
        for (int i = tid; i < 192; i += 128)
            xin[i] = g_x[(b * TF + t + (i >> 6)) * 64 + (i & 63)];
        __syncthreads();
        float acc = 0.0f;
        const float* w = wc + tid * 193;
#pragma unroll 8
        for (int ic = 0; ic < 64; ic++) {
            acc = fmaf(w[ic * 3 + 0], xin[ic], acc);
            acc = fmaf(w[ic * 3 + 1], xin[64 + ic], acc);
            acc = fmaf(w[ic * 3 + 2], xin[128 + ic], acc);
        }
        g_y[(b * TC + t) * 128 + tid] = tanhf(acc);
        __syncthreads();
    }
}

// ---------------- fd2 + gains: weight-stationary, 1 block per batch elem ----------------
#define FD2_SMEM ((320 * 129 + 128 + 320 + 80) * 4)
__global__ void k_fd2n(const float* __restrict__ fd2, const float* __restrict__ cg_w,
                       const float* __restrict__ cg_b) {
    int b = blockIdx.x;
    extern __shared__ float smf[];
    float* wf = smf;                       // 320 x 129 (padded)
    float* ybuf = wf + 320 * 129;          // 128
    float* condb = ybuf + 128;             // 320
    float* cgw = condb + 320;              // 80
    int tid = threadIdx.x;                 // 320
    for (int i = tid; i < 320 * 128; i += 320) {
        int o = i >> 7, k = i & 127;
        wf[o * 129 + k] = fd2[i];
    }
    if (tid < 80) cgw[tid] = cg_w[tid];
    __syncthreads();
    float cb = cg_b[0];
    for (int t = 0; t < TC; t++) {
        if (tid < 128) ybuf[tid] = g_y[(b * TC + t) * 128 + tid];
        __syncthreads();
        float acc = 0.0f;
        const float* w = wf + tid * 129;
#pragma unroll 8
        for (int k = 0; k < 128; k++) acc = fmaf(w[k], ybuf[k], acc);
        float cv = tanhf(acc);
        condb[tid] = cv;
        g_cond[((size_t)(b * TC + t)) * 320 + tid] = cv;
        __syncthreads();
        if (tid < 4) {
            float a = cb;
            const float* cc = condb + tid * 80;
#pragma unroll 8
            for (int k = 0; k < 80; k++) a = fmaf(cgw[k], cc[k], a);
            float g = 0.2f + 0.8f * sigf(a);
            g = fminf(fmaxf(g, 0.001f), 20.0f);
            g_gain[(t * 4 + tid) * BATCH + b] = g;
        }
    }
}

// ================= R4 scan (proven 73.8ms) — verbatim =================
template <int IN, int OUT, int ACT>
__device__ __forceinline__ void matvec(const float* __restrict__ Wt,
                                       const float* __restrict__ x0, const float* __restrict__ x1,
                                       float* __restrict__ y0, float* __restrict__ y1,
                                       float* __restrict__ red) {
    constexpr int RG = OUT / 4;                      // float4 row-groups
    constexpr int S0 = NT / RG;
    constexpr int S = (S0 > 32) ? 32 : S0;           // k-slices
    int tid = threadIdx.x;
    int sl = tid / RG;
    int rg = tid - sl * RG;
    if (sl < S) {
        float4 a0 = make_float4(0.f, 0.f, 0.f, 0.f);
        float4 a1 = make_float4(0.f, 0.f, 0.f, 0.f);
        const float4* __restrict__ W4 = reinterpret_cast<const float4*>(Wt) + rg;
#pragma unroll 16
        for (int k = sl; k < IN; k += S) {
            float xk0 = x0[k], xk1 = x1[k];
            float4 w = __ldg(&W4[k * RG]);
            a0.x = fmaf(w.x, xk0, a0.x); a0.y = fmaf(w.y, xk0, a0.y);
            a0.z = fmaf(w.z, xk0, a0.z); a0.w = fmaf(w.w, xk0, a0.w);
            a1.x = fmaf(w.x, xk1, a1.x); a1.y = fmaf(w.y, xk1, a1.y);
            a1.z = fmaf(w.z, xk1, a1.z); a1.w = fmaf(w.w, xk1, a1.w);
        }
        float4* r0 = reinterpret_cast<float4*>(red + sl * OUT) + rg;
        float4* r1 = reinterpret_cast<float4*>(red + 2048 + sl * OUT) + rg;
        *r0 = a0; *r1 = a1;
    }
    __syncthreads();
    for (int o = tid; o < 2 * OUT; o += NT) {
        int bb = o / OUT, j = o - bb * OUT;
        const float* r = red + bb * 2048;
        float t = 0.0f;
#pragma unroll
        for (int ss = 0; ss < S; ss++) t += r[ss * OUT + j];
        if (ACT == 1) t = tanhf(t);
        float* y = bb ? y1 : y0;
        y[j] = t;
    }
    __syncthreads();
}

template <int H, int IN>
__device__ __forceinline__ void gru_glu(const float* Wih, const float* Whh, const float* Wglu,
                                        const float* x0, const float* x1,
                                        float* h0, float* h1, float* g0, float* g1,
                                        float* gi0, float* gi1, float* gh0, float* gh1,
                                        float* red) {
    matvec<IN, 3 * H, 0>(Wih, x0, x1, gi0, gi1, red);
    matvec<H, 3 * H, 0>(Whh, h0, h1, gh0, gh1, red);
    int tid = threadIdx.x;
    for (int i = tid; i < 2 * H; i += NT) {
        int bb = i / H, o = i - bb * H;
        const float* gi = bb ? gi1 : gi0;
        const float* gh = bb ? gh1 : gh0;
        float* h = bb ? h1 : h0;
        float r = sigf(gi[o] + gh[o]);
        float z = sigf(gi[H + o] + gh[H + o]);
        float n = tanhf(gi[2 * H + o] + r * gh[2 * H + o]);
        h[o] = (1.0f - z) * n + z * h[o];
    }
    __syncthreads();
    matvec<H, H, 0>(Wglu, h0, h1, gh0, gh1, red);
    for (int i = tid; i < 2 * H; i += NT) {
        int bb = i / H, o = i - bb * H;
        const float* h = bb ? h1 : h0;
        const float* u = bb ? gh1 : gh0;
        float* g = bb ? g1 : g0;
        g[o] = h[o] * sigf(u[o]);
    }
    __syncthreads();
}

__global__ __launch_bounds__(NT) void k_scan(const int* __restrict__ period,
                                             const float* __restrict__ gout_b,
                                             float* __restrict__ out) {
    int b0 = blockIdx.x * 2;
    __shared__ __align__(16) float exc[2][256];
    __shared__ __align__(16) float xcat[2][328];   // [0:164) state, [164:328) tmp
    __shared__ __align__(16) float s1[2][160], s2[2][128], s3[2][128];
    __shared__ __align__(16) float buf_t[2][192];  // tanh pre-glu buffer (fwc / skip)
    __shared__ __align__(16) float fwc_out[2][192];
    __shared__ __align__(16) float gi[2][480], gh[2][480];
    __shared__ __align__(16) float g1b[2][160], g2b[2][128], g3b[2][128];
    __shared__ __align__(16) float skin[2][688];   // GRU inputs + skip_in
    __shared__ __align__(16) float skipv[2][128];
    __shared__ __align__(16) float pgb[2][4];
    __shared__ __align__(16) float red[4096];
    __shared__ float sgain[2];
    __shared__ int   sper[2];
    int tid = threadIdx.x;

    for (int i = tid; i < 2 * 256; i += NT) ((float*)exc)[i] = 0.0f;
    for (int i = tid; i < 2 * 328; i += NT) ((float*)xcat)[i] = 0.0f;
    for (int i = tid; i < 2 * 160; i += NT) ((float*)s1)[i] = 0.0f;
    for (int i = tid; i < 2 * 128; i += NT) ((float*)s2)[i] = 0.0f;
    for (int i = tid; i < 2 * 128; i += NT) ((float*)s3)[i] = 0.0f;
    __syncthreads();

    int base = 0;  // exc circular base
    for (int s = 0; s < NSTEP; s++) {
        int frame = s >> 2, sub = s & 3;
        if (tid < 4) {
            int bb = tid >> 1;
            if (tid & 1) {
                int p = period[(b0 + bb) * TT + 3 + frame];
                sper[bb] = min(max(p, 32), 254);
            } else {
                sgain[bb] = g_gain[s * BATCH + b0 + bb];
            }
        }
        if (tid < 328) {
            int bb = tid >= 164;
            int j = bb ? tid - 164 : tid;
            xcat[bb][j] = xcat[bb][164 + j];
        }
        __syncthreads();
        if (tid < 328) {
            int bb = tid >= 164;
            int j = bb ? tid - 164 : tid;
            float invg = 1.0f / (1e-5f + sgain[bb]);
            float v;
            if (j < 80) {
                v = g_cond[((size_t)((b0 + bb) * TC + frame)) * 320 + sub * 80 + j];
            } else if (j < 124) {
                int i2 = j - 80;
                int idx = 254 - sper[bb] + i2;
                if (idx >= 256) idx -= sper[bb];
                idx = max(0, min(255, idx));
                v = exc[bb][(base + idx) & 255] * invg;
            } else {
                v = exc[bb][(base + 216 + (j - 124)) & 255] * invg;
            }
            xcat[bb][164 + j] = v;
        }
        __syncthreads();

        matvec<328, 192, 1>(g_wt + OFF_FWC, xcat[0], xcat[1], buf_t[0], buf_t[1], red);
        matvec<192, 192, 0>(g_wt + OFF_FWCG, buf_t[0], buf_t[1], gh[0], gh[1], red);
        for (int i = tid; i < 2 * 192; i += NT) {
            int bb = i / 192, j = i - bb * 192;
            fwc_out[bb][j] = buf_t[bb][j] * sigf(gh[bb][j]);
        }
        __syncthreads();

        matvec<192, 4, 0>(g_wt + OFF_GOUT, fwc_out[0], fwc_out[1], pgb[0], pgb[1], red);
        if (tid < 8) {
            int bb = tid >> 2, j = tid & 3;
            pgb[bb][j] = sigf(pgb[bb][j] + gout_b[j]);
        }
        __syncthreads();

        for (int i = tid; i < 2 * 272; i += NT) {
            int bb = i / 272, j = i - bb * 272;
            float v;
            if (j < 192) v = fwc_out[bb][j];
            else if (j < 232) v = pgb[bb][0] * xcat[bb][164 + 82 + (j - 192)];
            else v = xcat[bb][164 + 124 + (j - 232)];
            skin[bb][j] = v;
        }
        __syncthreads();
        gru_glu<160, 272>(g_wt + OFF_G1IH, g_wt + OFF_G1HH, g_wt + OFF_GLU1,
                          skin[0], skin[1], s1[0], s1[1], g1b[0], g1b[1],
                          gi[0], gi[1], gh[0], gh[1], red);

        for (int i = tid; i < 2 * 240; i += NT) {
            int bb = i / 240, j = i - bb * 240;
            float v;
            if (j < 160) v = g1b[bb][j];
            else if (j < 200) v = pgb[bb][1] * xcat[bb][164 + 82 + (j - 160)];
            else v = xcat[bb][164 + 124 + (j - 200)];
            skin[bb][j] = v;
        }
        __syncthreads();
        gru_glu<128, 240>(g_wt + OFF_G2IH, g_wt + OFF_G2HH, g_wt + OFF_GLU2,
                          skin[0], skin[1], s2[0], s2[1], g2b[0], g2b[1],
                          gi[0], gi[1], gh[0], gh[1], red);

        for (int i = tid; i < 2 * 208; i += NT) {
            int bb = i / 208, j = i - bb * 208;
            float v;
            if (j < 128) v = g2b[bb][j];
            else if (j < 168) v = pgb[bb][2] * xcat[bb][164 + 82 + (j - 128)];
            else v = xcat[bb][164 + 124 + (j - 168)];
            skin[bb][j] = v;
        }
        __syncthreads();
        gru_glu<128, 208>(g_wt + OFF_G3IH, g_wt + OFF_G3HH, g_wt + OFF_GLU3,
                          skin[0], skin[1], s3[0], s3[1], g3b[0], g3b[1],
                          gi[0], gi[1], gh[0], gh[1], red);

        for (int i = tid; i < 2 * 688; i += NT) {
            int bb = i / 688, j = i - bb * 688;
            float v;
            if (j < 160) v = g1b[bb][j];
            else if (j < 288) v = g2b[bb][j - 160];
            else if (j < 416) v = g3b[bb][j - 288];
            else if (j < 608) v = fwc_out[bb][j - 416];
            else if (j < 648) v = pgb[bb][3] * xcat[bb][164 + 82 + (j - 608)];
            else v = xcat[bb][164 + 124 + (j - 648)];
            skin[bb][j] = v;
        }
        __syncthreads();
        matvec<688, 128, 1>(g_wt + OFF_SKIP, skin[0], skin[1], buf_t[0], buf_t[1], red);
        matvec<128, 128, 0>(g_wt + OFF_SKIPG, buf_t[0], buf_t[1], gh[0], gh[1], red);
        for (int i = tid; i < 2 * 128; i += NT) {
            int bb = i / 128, j = i - bb * 128;
            skipv[bb][j] = buf_t[bb][j] * sigf(gh[bb][j]);
        }
        __syncthreads();

        matvec<128, 40, 1>(g_wt + OFF_SIG, skipv[0], skipv[1], gi[0], gi[1], red);
        for (int i = tid; i < 2 * 40; i += NT) {
            int bb = i / 40, j = i - bb * 40;
            float v = gi[bb][j] * sgain[bb];
            exc[bb][(base + j) & 255] = v;   // becomes logical [216+j] after base shift
            out[(size_t)(b0 + bb) * 80000 + s * 40 + j] = v;
        }
        __syncthreads();
        base = (base + 40) & 255;
    }
}

// ---------------- launch ----------------
extern "C" void kernel_launch(void* const* d_in, const int* in_sizes, int n_in,
                              void* d_out, int out_size) {
    const float* features = (const float*)d_in[0];
    const int*   period   = (const int*)d_in[1];
    const float* pembed   = (const float*)d_in[2];
    const float* fd1_w    = (const float*)d_in[3];
    const float* fconv1_w = (const float*)d_in[4];
    const float* fd2_w    = (const float*)d_in[5];
    const float* cg_w     = (const float*)d_in[6];
    const float* cg_b     = (const float*)d_in[7];
    const float* gout_b   = (const float*)d_in[23];
    float* out = (float*)d_out;

    WP wp;
    for (int i = 0; i < 15; i++) wp.p[i] = (const float*)d_in[8 + i];

    cudaFuncSetAttribute(k_convn, cudaFuncAttributeMaxDynamicSharedMemorySize, CONV_SMEM);
    cudaFuncSetAttribute(k_fd2n, cudaFuncAttributeMaxDynamicSharedMemorySize, FD2_SMEM);

    dim3 tg((130560 + 255) / 256, 15);   // max layer elems = 480*272
    k_transpose_all<<<tg, 256>>>(wp);
    k_fd1n<<<BATCH, 256>>>(features, period, pembed, fd1_w);
    k_convn<<<dim3(BATCH, 2), 128, CONV_SMEM>>>(fconv1_w);
    k_fd2n<<<BATCH, 320, FD2_SMEM>>>(fd2_w, cg_w, cg_b);
    k_scan<<<BATCH / 2, NT>>>(period, gout_b, out);
    (void)in_sizes; (void)n_in; (void)out_size;
}